// round 9
// baseline (speedup 1.0000x reference)
#include <cuda_runtime.h>
#include <cuda_bf16.h>
#include <math.h>
#include <stdint.h>

#define NN 50000
#define NE 800000
#define HDIM 64
#define NBLK 196   // csr kernel grid; all blocks co-resident

#define EI_OFF  3200000LL
#define AL_OFF  4800000LL

// ---------------- scratch (static device globals; no allocation) ----------------
__device__ int   g_src[NE];
__device__ int   g_dst[NE];
__device__ int   g_deg[NN];
__device__ int   g_rowstart[NN + 1];
__device__ int   g_cursor[NN];
__device__ int   g_elist[NE];
__device__ int   g_part[256];
__device__ float g_xl[NN * HDIM];
__device__ float g_xr[NN * HDIM];
__device__ float g_res[NN * HDIM];
__device__ float g_score[NE * 4];       // per-(edge,head) scores, written by k_score
__device__ unsigned g_cnt;
__device__ unsigned g_gen;

// ---------------- K0: convert (+int64 detect) + degree histogram + ei passthrough ----------------
__global__ void k_convert(const int* __restrict__ ei, float* __restrict__ out, int write_ei) {
    __shared__ int s64;
    if (threadIdx.x == 0) {
        int f = 1;
#pragma unroll
        for (int i = 0; i < 16; i++) f &= (ei[2 * i + 1] == 0);
        s64 = f;
    }
    __syncthreads();
    int is64 = s64;
    int e = blockIdx.x * blockDim.x + threadIdx.x;
    if (e < NE) {
        int s, d;
        if (is64) {
            s = ei[2 * e];
            d = ei[2 * (NE + e)];
        } else {
            s = ei[e];
            d = ei[NE + e];
        }
        g_src[e] = s;
        g_dst[e] = d;
        atomicAdd(&g_deg[d], 1);
        if (write_ei) {
            out[EI_OFF + e]      = (float)s;
            out[EI_OFF + NE + e] = (float)d;
        }
    }
}

// ---------------- K1a: xl/xr GEMMs, 64-row tiles, 32 rows/warp (fma-bound ratio) ----------------
// 128 threads = 4 warps: mat = warp&1 (0=Wl,1=Wr), rh = warp>>1 (32 rows each).
__global__ void __launch_bounds__(128) k_proj2(
    const float* __restrict__ x,
    const float* __restrict__ Wl, const float* __restrict__ bl,
    const float* __restrict__ Wr, const float* __restrict__ br)
{
    __shared__ __align__(16) float sx[128 * 64];  // [k][r], r stride 64
    int tid = threadIdx.x;
    int lane = tid & 31;
    int warp = tid >> 5;
    int row0 = blockIdx.x * 64;
    const float4* x4 = reinterpret_cast<const float4*>(x);
    for (int idx = tid; idx < 2048; idx += 128) {
        int r = idx & 63, c4 = idx >> 6;
        int row = row0 + r;
        float4 v = make_float4(0.f, 0.f, 0.f, 0.f);
        if (row < NN) v = x4[row * 32 + c4];
        int k = c4 * 4;
        sx[(k + 0) * 64 + r] = v.x;
        sx[(k + 1) * 64 + r] = v.y;
        sx[(k + 2) * 64 + r] = v.z;
        sx[(k + 3) * 64 + r] = v.w;
    }
    __syncthreads();

    int mat = warp & 1;
    int rh  = warp >> 1;     // rows [rh*32, rh*32+32)
    const float* W = mat ? Wr : Wl;
    const float* B = mat ? br : bl;
    float* Out = mat ? g_xr : g_xl;
    int j0 = lane, j1 = lane + 32;

    unsigned long long acc0[16], acc1[16];
#pragma unroll
    for (int i = 0; i < 16; i++) { acc0[i] = 0ULL; acc1[i] = 0ULL; }

#pragma unroll 2
    for (int k = 0; k < 128; k++) {
        float w0 = W[k * 64 + j0];
        float w1 = W[k * 64 + j1];
        unsigned long long wd0, wd1;
        asm("mov.b64 %0, {%1, %2};" : "=l"(wd0) : "f"(w0), "f"(w0));
        asm("mov.b64 %0, {%1, %2};" : "=l"(wd1) : "f"(w1), "f"(w1));
        const ulonglong2* xp =
            reinterpret_cast<const ulonglong2*>(&sx[k * 64 + rh * 32]);
#pragma unroll
        for (int rq = 0; rq < 8; rq++) {
            ulonglong2 xv = xp[rq];   // LDS.128 broadcast
            asm("fma.rn.f32x2 %0, %1, %2, %0;" : "+l"(acc0[2*rq])   : "l"(xv.x), "l"(wd0));
            asm("fma.rn.f32x2 %0, %1, %2, %0;" : "+l"(acc1[2*rq])   : "l"(xv.x), "l"(wd1));
            asm("fma.rn.f32x2 %0, %1, %2, %0;" : "+l"(acc0[2*rq+1]) : "l"(xv.y), "l"(wd0));
            asm("fma.rn.f32x2 %0, %1, %2, %0;" : "+l"(acc1[2*rq+1]) : "l"(xv.y), "l"(wd1));
        }
    }

    float b0 = B[j0], b1 = B[j1];
#pragma unroll
    for (int rp = 0; rp < 16; rp++) {
        int row = row0 + rh * 32 + 2 * rp;
        float lo0 = __uint_as_float((unsigned)(acc0[rp] & 0xffffffffULL)) + b0;
        float hi0 = __uint_as_float((unsigned)(acc0[rp] >> 32)) + b0;
        float lo1 = __uint_as_float((unsigned)(acc1[rp] & 0xffffffffULL)) + b1;
        float hi1 = __uint_as_float((unsigned)(acc1[rp] >> 32)) + b1;
        if (row < NN)     { Out[row * 64 + j0] = lo0; Out[row * 64 + j1] = lo1; }
        if (row + 1 < NN) { Out[(row + 1) * 64 + j0] = hi0; Out[(row + 1) * 64 + j1] = hi1; }
    }
}

// ---------------- K1b: residual projection Wres (overlaps everything) ----------------
__global__ void __launch_bounds__(64) k_res(
    const float* __restrict__ x,
    const float* __restrict__ Wres, const float* __restrict__ bres)
{
    __shared__ __align__(16) float sx[128 * 32];
    int tid = threadIdx.x;
    int lane = tid & 31;
    int rh = tid >> 5;
    int row0 = blockIdx.x * 32;
    const float4* x4 = reinterpret_cast<const float4*>(x);
    for (int idx = tid; idx < 1024; idx += 64) {
        int r = idx & 31, c4 = idx >> 5;
        int row = row0 + r;
        float4 v = make_float4(0.f, 0.f, 0.f, 0.f);
        if (row < NN) v = x4[row * 32 + c4];
        int k = c4 * 4;
        sx[(k + 0) * 32 + r] = v.x;
        sx[(k + 1) * 32 + r] = v.y;
        sx[(k + 2) * 32 + r] = v.z;
        sx[(k + 3) * 32 + r] = v.w;
    }
    __syncthreads();

    int j0 = lane, j1 = lane + 32;
    unsigned long long acc0[8], acc1[8];
#pragma unroll
    for (int i = 0; i < 8; i++) { acc0[i] = 0ULL; acc1[i] = 0ULL; }

#pragma unroll 2
    for (int k = 0; k < 128; k++) {
        float w0 = Wres[k * 64 + j0];
        float w1 = Wres[k * 64 + j1];
        unsigned long long wd0, wd1;
        asm("mov.b64 %0, {%1, %2};" : "=l"(wd0) : "f"(w0), "f"(w0));
        asm("mov.b64 %0, {%1, %2};" : "=l"(wd1) : "f"(w1), "f"(w1));
        const ulonglong2* xp =
            reinterpret_cast<const ulonglong2*>(&sx[k * 32 + rh * 16]);
#pragma unroll
        for (int rq = 0; rq < 4; rq++) {
            ulonglong2 xv = xp[rq];
            asm("fma.rn.f32x2 %0, %1, %2, %0;" : "+l"(acc0[2*rq])   : "l"(xv.x), "l"(wd0));
            asm("fma.rn.f32x2 %0, %1, %2, %0;" : "+l"(acc1[2*rq])   : "l"(xv.x), "l"(wd1));
            asm("fma.rn.f32x2 %0, %1, %2, %0;" : "+l"(acc0[2*rq+1]) : "l"(xv.y), "l"(wd0));
            asm("fma.rn.f32x2 %0, %1, %2, %0;" : "+l"(acc1[2*rq+1]) : "l"(xv.y), "l"(wd1));
        }
    }

    float b0 = bres[j0], b1 = bres[j1];
#pragma unroll
    for (int rp = 0; rp < 8; rp++) {
        int row = row0 + rh * 16 + 2 * rp;
        float lo0 = __uint_as_float((unsigned)(acc0[rp] & 0xffffffffULL)) + b0;
        float hi0 = __uint_as_float((unsigned)(acc0[rp] >> 32)) + b0;
        float lo1 = __uint_as_float((unsigned)(acc1[rp] & 0xffffffffULL)) + b1;
        float hi1 = __uint_as_float((unsigned)(acc1[rp] >> 32)) + b1;
        if (row < NN)     { g_res[row * 64 + j0] = lo0; g_res[row * 64 + j1] = lo1; }
        if (row + 1 < NN) { g_res[(row + 1) * 64 + j0] = hi0; g_res[(row + 1) * 64 + j1] = hi1; }
    }
}

// ---------------- grid-wide barrier ----------------
__device__ __forceinline__ void gsync() {
    __threadfence();
    __syncthreads();
    if (threadIdx.x == 0) {
        unsigned gen = atomicAdd(&g_gen, 0u);
        if (atomicInc(&g_cnt, NBLK - 1u) == NBLK - 1u) {
            atomicAdd(&g_gen, 1u);
        } else {
            while (atomicAdd(&g_gen, 0u) == gen) { }
        }
    }
    __syncthreads();
}

// ---------------- K2: fused CSR build ----------------
__global__ void __launch_bounds__(256) k_csr() {
    __shared__ int s[256];
    __shared__ int sp[256];
    int t = threadIdx.x;
    int b = blockIdx.x;
    int idx = b * 256 + t;
    int v = (idx < NN) ? g_deg[idx] : 0;

    s[t] = v;
    __syncthreads();
#pragma unroll
    for (int off = 128; off > 0; off >>= 1) {
        if (t < off) s[t] += s[t + off];
        __syncthreads();
    }
    if (t == 0) g_part[b] = s[0];
    gsync();

    sp[t] = (t < NBLK) ? g_part[t] : 0;
    s[t] = v;
    __syncthreads();
#pragma unroll
    for (int off = 1; off < 256; off <<= 1) {
        int u1 = (t >= off) ? sp[t - off] : 0;
        int u2 = (t >= off) ? s[t - off] : 0;
        __syncthreads();
        sp[t] += u1;
        s[t]  += u2;
        __syncthreads();
    }
    int blk_off = (b == 0) ? 0 : sp[b - 1];
    int excl = s[t] - v + blk_off;
    if (idx < NN) {
        g_rowstart[idx] = excl;
        g_cursor[idx]   = excl;
    }
    if (b == 0 && t == 0) g_rowstart[NN] = sp[NBLK - 1];
    gsync();

    for (int e = b * 256 + t; e < NE; e += NBLK * 256) {
        int d = g_dst[e];
        int pos = atomicAdd(&g_cursor[d], 1);
        g_elist[pos] = e;
    }
}

// ---------------- K3: edge-parallel score kernel ----------------
// lane = eslot*4 + h: 8 edges x 4 heads per warp. Pure function of edge -> no sync,
// no sort, fully independent loads. Writes g_score[e*4+h] coalesced.
__global__ void __launch_bounds__(128) k_score(
    const float* __restrict__ edge_attr,
    const float* __restrict__ We,
    const float* __restrict__ att)
{
    __shared__ __align__(16) float sWA[160];   // We at [h*20+j], att at [80+h*20+j]
    int tid = threadIdx.x;
    if (tid < 64) {
        int hh = tid >> 4, jj = tid & 15;
        sWA[hh * 20 + jj] = We[tid];
    } else {
        int u = tid - 64;
        int hh = u >> 4, jj = u & 15;
        sWA[80 + hh * 20 + jj] = att[u];
    }
    __syncthreads();

    int warp = tid >> 5;
    int lane = tid & 31;
    int h = lane & 3;
    int eslot = lane >> 2;
    long long base = ((long long)blockIdx.x * 4 + warp) * 8;   // NE % 8 == 0, grid covers exactly
    int e = (int)base + eslot;

    int s = g_src[e];
    int d = g_dst[e];
    float ea = edge_attr[e];

    const float4* xlp = (const float4*)&g_xl[s * 64 + h * 16];
    const float4* xrp = (const float4*)&g_xr[d * 64 + h * 16];
    const float4* pWe = (const float4*)&sWA[h * 20];
    const float4* pAt = (const float4*)&sWA[80 + h * 20];

    float p;
    {
#define LRELU(v) (fmaxf((v), 0.f) + 0.2f * fminf((v), 0.f))
        float f;
        float4 a, r, w, tt;
        a = xlp[0]; r = xrp[0]; w = pWe[0]; tt = pAt[0];
        f = fmaf(ea, w.x, a.x + r.x); p = tt.x * LRELU(f);
        f = fmaf(ea, w.y, a.y + r.y); p = fmaf(tt.y, LRELU(f), p);
        f = fmaf(ea, w.z, a.z + r.z); p = fmaf(tt.z, LRELU(f), p);
        f = fmaf(ea, w.w, a.w + r.w); p = fmaf(tt.w, LRELU(f), p);
        a = xlp[1]; r = xrp[1]; w = pWe[1]; tt = pAt[1];
        f = fmaf(ea, w.x, a.x + r.x); p = fmaf(tt.x, LRELU(f), p);
        f = fmaf(ea, w.y, a.y + r.y); p = fmaf(tt.y, LRELU(f), p);
        f = fmaf(ea, w.z, a.z + r.z); p = fmaf(tt.z, LRELU(f), p);
        f = fmaf(ea, w.w, a.w + r.w); p = fmaf(tt.w, LRELU(f), p);
        a = xlp[2]; r = xrp[2]; w = pWe[2]; tt = pAt[2];
        f = fmaf(ea, w.x, a.x + r.x); p = fmaf(tt.x, LRELU(f), p);
        f = fmaf(ea, w.y, a.y + r.y); p = fmaf(tt.y, LRELU(f), p);
        f = fmaf(ea, w.z, a.z + r.z); p = fmaf(tt.z, LRELU(f), p);
        f = fmaf(ea, w.w, a.w + r.w); p = fmaf(tt.w, LRELU(f), p);
        a = xlp[3]; r = xrp[3]; w = pWe[3]; tt = pAt[3];
        f = fmaf(ea, w.x, a.x + r.x); p = fmaf(tt.x, LRELU(f), p);
        f = fmaf(ea, w.y, a.y + r.y); p = fmaf(tt.y, LRELU(f), p);
        f = fmaf(ea, w.z, a.z + r.z); p = fmaf(tt.z, LRELU(f), p);
        f = fmaf(ea, w.w, a.w + r.w); p = fmaf(tt.w, LRELU(f), p);
#undef LRELU
    }
    g_score[base * 4 + lane] = p;    // == e*4 + h, fully coalesced
}

// ---------------- K4: node aggregation (tiny state, independent iterations) ----------------
// Warp per node; lane owns output dims (2l, 2l+1), head = l>>3.
__global__ void __launch_bounds__(128) k_aggr(
    const float* __restrict__ bias_out,
    float* __restrict__ out, int do_alpha)
{
    __shared__ int sbuf[4 * 128];
    int tid = threadIdx.x;
    int warp = tid >> 5;
    int lane = tid & 31;
    int n = blockIdx.x * 4 + warp;   // NN % 4 == 0
    int* buf = &sbuf[warp * 128];

    int start = g_rowstart[n];
    int deg = g_rowstart[n + 1] - start;

    // deterministic: sort this node's edge ids ascending
    if (deg <= 32) {
        int myid = (lane < deg) ? g_elist[start + lane] : 0x7fffffff;
        int rank = 0;
#pragma unroll
        for (int j = 0; j < 32; j++) {
            int o = __shfl_sync(0xffffffffu, myid, j);
            rank += (o < myid);
        }
        if (lane < deg) buf[rank] = myid;
    } else {
        int dd = min(deg, 128);
        for (int i = lane; i < dd; i += 32) {
            int vv = g_elist[start + i];
            int rank = 0;
            for (int j = 0; j < dd; j++) rank += (g_elist[start + j] < vv);
            buf[rank] = vv;
        }
    }
    __syncwarp();
    bool use_buf = (deg <= 128);

    int h = lane >> 3;
    const float NEG_INF = __int_as_float(0xff800000);

    // pass 1: max (order-free)
    float m = NEG_INF;
#pragma unroll 4
    for (int i = 0; i < deg; i++) {
        int e = use_buf ? buf[i] : g_elist[start + i];
        m = fmaxf(m, g_score[(long long)e * 4 + h]);
    }

    // pass 2: den + weighted aggregation (independent iterations)
    float den = 0.f, ax = 0.f, ay = 0.f;
#pragma unroll 4
    for (int i = 0; i < deg; i++) {
        int e = use_buf ? buf[i] : g_elist[start + i];
        int s = g_src[e];
        float p = g_score[(long long)e * 4 + h];
        float2 xl2 = *(const float2*)&g_xl[s * 64 + 2 * lane];
        float ex = __expf(p - m);
        den += ex;
        ax = fmaf(ex, xl2.x, ax);
        ay = fmaf(ex, xl2.y, ay);
    }

    float dfin = den + 1e-16f;
    float2 r2  = *(const float2*)&g_res[n * 64 + 2 * lane];
    float2 bo2 = *(const float2*)&bias_out[2 * lane];
    float ox = ax / dfin + bo2.x + r2.x;
    float oy = ay / dfin + bo2.y + r2.y;
    ox = ox > 0.f ? ox : expm1f(ox);
    oy = oy > 0.f ? oy : expm1f(oy);
    *(float2*)&out[n * 64 + 2 * lane] = make_float2(ox, oy);

    // reset degree counter for next call
    if (lane == 0) g_deg[n] = 0;

    if (do_alpha) {
        float m0 = __shfl_sync(0xffffffffu, m, 0);
        float m1 = __shfl_sync(0xffffffffu, m, 8);
        float m2 = __shfl_sync(0xffffffffu, m, 16);
        float m3 = __shfl_sync(0xffffffffu, m, 24);
        float d0 = __shfl_sync(0xffffffffu, den, 0)  + 1e-16f;
        float d1 = __shfl_sync(0xffffffffu, den, 8)  + 1e-16f;
        float d2 = __shfl_sync(0xffffffffu, den, 16) + 1e-16f;
        float d3 = __shfl_sync(0xffffffffu, den, 24) + 1e-16f;
        for (int i = lane; i < deg; i += 32) {
            int e = use_buf ? buf[i] : g_elist[start + i];
            float4 s4 = *(const float4*)&g_score[(long long)e * 4];
            float4 a;
            a.x = __expf(s4.x - m0) / d0;
            a.y = __expf(s4.y - m1) / d1;
            a.z = __expf(s4.z - m2) / d2;
            a.w = __expf(s4.w - m3) / d3;
            *(float4*)&out[AL_OFF + (long long)e * 4] = a;
        }
    }
}

// ---------------- launch ----------------
extern "C" void kernel_launch(void* const* d_in, const int* in_sizes, int n_in,
                              void* d_out, int out_size) {
    const float* x         = (const float*)d_in[0];
    const int*   ei        = (const int*)d_in[1];
    const float* edge_attr = (const float*)d_in[2];
    const float* Wl        = (const float*)d_in[3];
    const float* bl        = (const float*)d_in[4];
    const float* Wr        = (const float*)d_in[5];
    const float* br        = (const float*)d_in[6];
    const float* We        = (const float*)d_in[7];
    const float* att       = (const float*)d_in[8];
    const float* bias_out  = (const float*)d_in[9];
    const float* Wres      = (const float*)d_in[10];
    const float* bres      = (const float*)d_in[11];
    float* out = (float*)d_out;

    int write_ei = (out_size >= 4800000);
    int do_alpha = (out_size >= 8000000);

    static cudaStream_t s2 = 0, s3 = 0;
    static cudaEvent_t evA = 0, evConv = 0, evScore = 0, evRes = 0;
    if (!s2) {
        cudaStreamCreateWithFlags(&s2, cudaStreamNonBlocking);
        cudaStreamCreateWithFlags(&s3, cudaStreamNonBlocking);
        cudaEventCreateWithFlags(&evA, cudaEventDisableTiming);
        cudaEventCreateWithFlags(&evConv, cudaEventDisableTiming);
        cudaEventCreateWithFlags(&evScore, cudaEventDisableTiming);
        cudaEventCreateWithFlags(&evRes, cudaEventDisableTiming);
    }

    cudaEventRecord(evA, 0);
    cudaStreamWaitEvent(s2, evA, 0);
    cudaStreamWaitEvent(s3, evA, 0);

    // s2: xl/xr GEMM -> (after convert) edge-parallel scores
    k_proj2<<<(NN + 63) / 64, 128, 0, s2>>>(x, Wl, bl, Wr, br);
    // s3: residual GEMM (only needed by k_aggr epilogue)
    k_res<<<(NN + 31) / 32, 64, 0, s3>>>(x, Wres, bres);
    cudaEventRecord(evRes, s3);

    // stream 0: convert -> CSR
    k_convert<<<(NE + 255) / 256, 256>>>(ei, out, write_ei);
    cudaEventRecord(evConv, 0);
    k_csr<<<NBLK, 256>>>();

    // scores need proj2 (s2 order) + convert
    cudaStreamWaitEvent(s2, evConv, 0);
    k_score<<<NE / 32, 128, 0, s2>>>(edge_attr, We, att);
    cudaEventRecord(evScore, s2);

    // aggregation needs CSR (stream 0 order) + scores + residual
    cudaStreamWaitEvent(0, evScore, 0);
    cudaStreamWaitEvent(0, evRes, 0);
    k_aggr<<<NN / 4, 128>>>(bias_out, out, do_alpha);
}

// round 10
// speedup vs baseline: 1.0800x; 1.0800x over previous
#include <cuda_runtime.h>
#include <cuda_bf16.h>
#include <math.h>
#include <stdint.h>

#define NN 50000
#define NE 800000
#define HDIM 64
#define NBLK 196   // csr kernel grid; all blocks co-resident

#define EI_OFF  3200000LL
#define AL_OFF  4800000LL

typedef unsigned long long u64;

// ---------------- scratch (static device globals; no allocation) ----------------
// g_deg is zero at load and re-zeroed by k_node each call -> identical work every call.
__device__ int   g_src[NE];
__device__ int   g_dst[NE];
__device__ int   g_deg[NN];
__device__ int   g_rowstart[NN + 1];
__device__ int   g_cursor[NN];
__device__ int   g_elist[NE];
__device__ int   g_esrc[NE];      // src pre-gathered into CSR slot order
__device__ float g_eea[NE];       // edge_attr pre-gathered into CSR slot order
__device__ int   g_part[256];
__device__ float g_xl[NN * HDIM];
__device__ float g_xr[NN * HDIM];
__device__ float g_res[NN * HDIM];
__device__ float g_score[NE * 4]; // only for rare deg>128 fallback
__device__ unsigned g_cnt;
__device__ unsigned g_gen;

// ---------------- packed f32x2 helpers ----------------
__device__ __forceinline__ u64 pk2(float a, float b) {
    u64 r; asm("mov.b64 %0,{%1,%2};" : "=l"(r) : "f"(a), "f"(b)); return r;
}
__device__ __forceinline__ void upk2(u64 v, float& a, float& b) {
    asm("mov.b64 {%0,%1},%2;" : "=f"(a), "=f"(b) : "l"(v));
}
__device__ __forceinline__ u64 add2(u64 a, u64 b) {
    u64 r; asm("add.rn.f32x2 %0,%1,%2;" : "=l"(r) : "l"(a), "l"(b)); return r;
}
__device__ __forceinline__ u64 mul2(u64 a, u64 b) {
    u64 r; asm("mul.rn.f32x2 %0,%1,%2;" : "=l"(r) : "l"(a), "l"(b)); return r;
}
__device__ __forceinline__ u64 fma2(u64 a, u64 b, u64 c) {
    u64 r; asm("fma.rn.f32x2 %0,%1,%2,%3;" : "=l"(r) : "l"(a), "l"(b), "l"(c)); return r;
}

// ---------------- K0: convert (+int64 detect) + degree histogram + ei passthrough ----------------
__global__ void k_convert(const int* __restrict__ ei, float* __restrict__ out, int write_ei) {
    __shared__ int s64;
    if (threadIdx.x == 0) {
        int f = 1;
#pragma unroll
        for (int i = 0; i < 16; i++) f &= (ei[2 * i + 1] == 0);
        s64 = f;
    }
    __syncthreads();
    int is64 = s64;
    int e = blockIdx.x * blockDim.x + threadIdx.x;
    if (e < NE) {
        int s, d;
        if (is64) {
            s = ei[2 * e];
            d = ei[2 * (NE + e)];
        } else {
            s = ei[e];
            d = ei[NE + e];
        }
        g_src[e] = s;
        g_dst[e] = d;
        atomicAdd(&g_deg[d], 1);
        if (write_ei) {
            out[EI_OFF + e]      = (float)s;
            out[EI_OFF + NE + e] = (float)d;
        }
    }
}

// ---------------- K1a: xl/xr GEMMs, 256 threads, 64-row tiles, 16 rows/warp ----------------
// 8 warps: mat = warp&1 (0=Wl,1=Wr), rh = warp>>1 (rows [rh*16, rh*16+16)).
__global__ void __launch_bounds__(256) k_proj2(
    const float* __restrict__ x,
    const float* __restrict__ Wl, const float* __restrict__ bl,
    const float* __restrict__ Wr, const float* __restrict__ br)
{
    __shared__ __align__(16) float sx[128 * 64];  // [k][r]
    int tid = threadIdx.x;
    int lane = tid & 31;
    int warp = tid >> 5;
    int row0 = blockIdx.x * 64;
    const float4* x4 = reinterpret_cast<const float4*>(x);
    for (int idx = tid; idx < 2048; idx += 256) {
        int r = idx & 63, c4 = idx >> 6;
        int row = row0 + r;
        float4 v = make_float4(0.f, 0.f, 0.f, 0.f);
        if (row < NN) v = x4[row * 32 + c4];
        int k = c4 * 4;
        sx[(k + 0) * 64 + r] = v.x;
        sx[(k + 1) * 64 + r] = v.y;
        sx[(k + 2) * 64 + r] = v.z;
        sx[(k + 3) * 64 + r] = v.w;
    }
    __syncthreads();

    int mat = warp & 1;
    int rh  = warp >> 1;     // 0..3
    const float* W = mat ? Wr : Wl;
    const float* B = mat ? br : bl;
    float* Out = mat ? g_xr : g_xl;
    int j0 = lane, j1 = lane + 32;

    u64 acc0[8], acc1[8];
#pragma unroll
    for (int i = 0; i < 8; i++) { acc0[i] = 0ULL; acc1[i] = 0ULL; }

#pragma unroll 2
    for (int k = 0; k < 128; k++) {
        float w0 = W[k * 64 + j0];
        float w1 = W[k * 64 + j1];
        u64 wd0 = pk2(w0, w0), wd1 = pk2(w1, w1);
        const ulonglong2* xp =
            reinterpret_cast<const ulonglong2*>(&sx[k * 64 + rh * 16]);
#pragma unroll
        for (int rq = 0; rq < 4; rq++) {
            ulonglong2 xv = xp[rq];   // LDS.128 broadcast
            asm("fma.rn.f32x2 %0, %1, %2, %0;" : "+l"(acc0[2*rq])   : "l"(xv.x), "l"(wd0));
            asm("fma.rn.f32x2 %0, %1, %2, %0;" : "+l"(acc1[2*rq])   : "l"(xv.x), "l"(wd1));
            asm("fma.rn.f32x2 %0, %1, %2, %0;" : "+l"(acc0[2*rq+1]) : "l"(xv.y), "l"(wd0));
            asm("fma.rn.f32x2 %0, %1, %2, %0;" : "+l"(acc1[2*rq+1]) : "l"(xv.y), "l"(wd1));
        }
    }

    float b0 = B[j0], b1 = B[j1];
#pragma unroll
    for (int rp = 0; rp < 8; rp++) {
        int row = row0 + rh * 16 + 2 * rp;
        float l0, h0, l1, h1;
        upk2(acc0[rp], l0, h0);
        upk2(acc1[rp], l1, h1);
        l0 += b0; h0 += b0; l1 += b1; h1 += b1;
        if (row < NN)     { Out[row * 64 + j0] = l0; Out[row * 64 + j1] = l1; }
        if (row + 1 < NN) { Out[(row + 1) * 64 + j0] = h0; Out[(row + 1) * 64 + j1] = h1; }
    }
}

// ---------------- K1b: residual projection Wres (overlaps everything) ----------------
__global__ void __launch_bounds__(64) k_res(
    const float* __restrict__ x,
    const float* __restrict__ Wres, const float* __restrict__ bres)
{
    __shared__ __align__(16) float sx[128 * 32];
    int tid = threadIdx.x;
    int lane = tid & 31;
    int rh = tid >> 5;
    int row0 = blockIdx.x * 32;
    const float4* x4 = reinterpret_cast<const float4*>(x);
    for (int idx = tid; idx < 1024; idx += 64) {
        int r = idx & 31, c4 = idx >> 5;
        int row = row0 + r;
        float4 v = make_float4(0.f, 0.f, 0.f, 0.f);
        if (row < NN) v = x4[row * 32 + c4];
        int k = c4 * 4;
        sx[(k + 0) * 32 + r] = v.x;
        sx[(k + 1) * 32 + r] = v.y;
        sx[(k + 2) * 32 + r] = v.z;
        sx[(k + 3) * 32 + r] = v.w;
    }
    __syncthreads();

    int j0 = lane, j1 = lane + 32;
    u64 acc0[8], acc1[8];
#pragma unroll
    for (int i = 0; i < 8; i++) { acc0[i] = 0ULL; acc1[i] = 0ULL; }

#pragma unroll 2
    for (int k = 0; k < 128; k++) {
        float w0 = Wres[k * 64 + j0];
        float w1 = Wres[k * 64 + j1];
        u64 wd0 = pk2(w0, w0), wd1 = pk2(w1, w1);
        const ulonglong2* xp =
            reinterpret_cast<const ulonglong2*>(&sx[k * 32 + rh * 16]);
#pragma unroll
        for (int rq = 0; rq < 4; rq++) {
            ulonglong2 xv = xp[rq];
            asm("fma.rn.f32x2 %0, %1, %2, %0;" : "+l"(acc0[2*rq])   : "l"(xv.x), "l"(wd0));
            asm("fma.rn.f32x2 %0, %1, %2, %0;" : "+l"(acc1[2*rq])   : "l"(xv.x), "l"(wd1));
            asm("fma.rn.f32x2 %0, %1, %2, %0;" : "+l"(acc0[2*rq+1]) : "l"(xv.y), "l"(wd0));
            asm("fma.rn.f32x2 %0, %1, %2, %0;" : "+l"(acc1[2*rq+1]) : "l"(xv.y), "l"(wd1));
        }
    }

    float b0 = bres[j0], b1 = bres[j1];
#pragma unroll
    for (int rp = 0; rp < 8; rp++) {
        int row = row0 + rh * 16 + 2 * rp;
        float l0, h0, l1, h1;
        upk2(acc0[rp], l0, h0);
        upk2(acc1[rp], l1, h1);
        l0 += b0; h0 += b0; l1 += b1; h1 += b1;
        if (row < NN)     { g_res[row * 64 + j0] = l0; g_res[row * 64 + j1] = l1; }
        if (row + 1 < NN) { g_res[(row + 1) * 64 + j0] = h0; g_res[(row + 1) * 64 + j1] = h1; }
    }
}

// ---------------- grid-wide barrier ----------------
__device__ __forceinline__ void gsync() {
    __threadfence();
    __syncthreads();
    if (threadIdx.x == 0) {
        unsigned gen = atomicAdd(&g_gen, 0u);
        if (atomicInc(&g_cnt, NBLK - 1u) == NBLK - 1u) {
            atomicAdd(&g_gen, 1u);
        } else {
            while (atomicAdd(&g_gen, 0u) == gen) { }
        }
    }
    __syncthreads();
}

// ---------------- K2: fused CSR build (+src/ea pre-gather into CSR order) ----------------
__global__ void __launch_bounds__(256) k_csr(const float* __restrict__ edge_attr) {
    __shared__ int s[256];
    __shared__ int sp[256];
    int t = threadIdx.x;
    int b = blockIdx.x;
    int idx = b * 256 + t;
    int v = (idx < NN) ? g_deg[idx] : 0;

    s[t] = v;
    __syncthreads();
#pragma unroll
    for (int off = 128; off > 0; off >>= 1) {
        if (t < off) s[t] += s[t + off];
        __syncthreads();
    }
    if (t == 0) g_part[b] = s[0];
    gsync();

    sp[t] = (t < NBLK) ? g_part[t] : 0;
    s[t] = v;
    __syncthreads();
#pragma unroll
    for (int off = 1; off < 256; off <<= 1) {
        int u1 = (t >= off) ? sp[t - off] : 0;
        int u2 = (t >= off) ? s[t - off] : 0;
        __syncthreads();
        sp[t] += u1;
        s[t]  += u2;
        __syncthreads();
    }
    int blk_off = (b == 0) ? 0 : sp[b - 1];
    int excl = s[t] - v + blk_off;
    if (idx < NN) {
        g_rowstart[idx] = excl;
        g_cursor[idx]   = excl;
    }
    if (b == 0 && t == 0) g_rowstart[NN] = sp[NBLK - 1];
    gsync();

    for (int e = b * 256 + t; e < NE; e += NBLK * 256) {
        int d = g_dst[e];
        int pos = atomicAdd(&g_cursor[d], 1);
        g_elist[pos] = e;
        g_esrc[pos]  = g_src[e];
        g_eea[pos]   = edge_attr[e];
    }
}

// ---------------- K3: per-node kernel, split-dim layout, packed f32x2 math ----------------
// Warp per node. lane = eslot*8 + h*2 + half. Each lane owns 8 dims of one (edge,head).
// Sort carries (e, src, ea) payloads -> inner loop is LDS -> LDG(xl) only.
// LeakyReLU(v) = 0.6v + 0.4|v| (packed).
__global__ void __launch_bounds__(128) k_node(
    const float* __restrict__ We,
    const float* __restrict__ att,
    const float* __restrict__ bias_out,
    float* __restrict__ out, int do_alpha)
{
    __shared__ int   sbuf[4 * 128];
    __shared__ int   sbsr[4 * 128];
    __shared__ float sbea[4 * 128];
    __shared__ __align__(16) float ssc[4][128 * 4];
    __shared__ __align__(16) float sacc[4][64];
    __shared__ __align__(16) float sWA[160];   // We at [h*20+j], att at [80+h*20+j]
    int tid = threadIdx.x;
    int warp = tid >> 5;
    int lane = tid & 31;

    if (tid < 64) {
        int hh = tid >> 4, jj = tid & 15;
        sWA[hh * 20 + jj] = We[tid];
    } else {
        int u = tid - 64;
        int hh = u >> 4, jj = u & 15;
        sWA[80 + hh * 20 + jj] = att[u];
    }
    __syncthreads();

    int n = blockIdx.x * 4 + warp;    // NN % 4 == 0
    int* buf  = &sbuf[warp * 128];
    int* bsr  = &sbsr[warp * 128];
    float* bea = &sbea[warp * 128];
    float* psc = ssc[warp];

    int start = g_rowstart[n];
    int deg = g_rowstart[n + 1] - start;

    // deterministic: sort edge ids ascending, carrying (src, ea) payloads
    if (deg <= 32) {
        int myid = 0x7fffffff, ms = 0;
        float mea = 0.f;
        if (lane < deg) {
            myid = g_elist[start + lane];
            ms   = g_esrc[start + lane];
            mea  = g_eea[start + lane];
        }
        int rank = 0;
#pragma unroll
        for (int j = 0; j < 32; j++) {
            int o = __shfl_sync(0xffffffffu, myid, j);
            rank += (o < myid);
        }
        if (lane < deg) { buf[rank] = myid; bsr[rank] = ms; bea[rank] = mea; }
    } else {
        int dd = min(deg, 128);
        for (int i = lane; i < dd; i += 32) {
            int vv = g_elist[start + i];
            int rank = 0;
            for (int j = 0; j < dd; j++) rank += (g_elist[start + j] < vv);
            buf[rank] = vv;
            bsr[rank] = g_esrc[start + i];
            bea[rank] = g_eea[start + i];
        }
    }
    __syncwarp();
    bool use_buf = (deg <= 128);

    int eslot = lane >> 3;          // 0..3
    int h     = (lane >> 1) & 3;    // 0..3
    int half  = lane & 1;           // 0..1
    int dbase = h * 16 + half * 8;  // this lane's 8-dim slice

    // packed per-lane constants (8B-aligned smem/global reads)
    const ulonglong2* xrp = (const ulonglong2*)&g_xr[n * 64 + dbase];
    ulonglong2 xrA = xrp[0], xrB = xrp[1];
    const u64* pWe = (const u64*)&sWA[h * 20 + half * 8];
    const u64* pAt = (const u64*)&sWA[80 + h * 20 + half * 8];
    u64 we0 = pWe[0], we1 = pWe[1], we2 = pWe[2], we3 = pWe[3];
    u64 at0 = pAt[0], at1 = pAt[1], at2 = pAt[2], at3 = pAt[3];
    const u64 ABSM = 0x7fffffff7fffffffULL;
    const u64 C06 = pk2(0.6f, 0.6f);
    const u64 C04 = pk2(0.4f, 0.4f);

    const float NEG_INF = __int_as_float(0xff800000);
    float m = NEG_INF;
    float den = 0.f;
    u64 acc[4] = {0ULL, 0ULL, 0ULL, 0ULL};

    for (int base = 0; base < deg; base += 4) {
        int ii = base + eslot;
        bool act = (ii < deg);
        int s = 0;
        float ea = 0.f;
        if (act) {
            if (use_buf) { s = bsr[ii]; ea = bea[ii]; }
            else         { s = g_esrc[start + ii]; ea = g_eea[start + ii]; }
        }
        const ulonglong2* xlp = (const ulonglong2*)&g_xl[s * 64 + dbase];
        ulonglong2 xA = xlp[0], xB = xlp[1];
        u64 ea2 = pk2(ea, ea);

        // packed 8-dim partial score
        u64 f, l, pacc;
        f = fma2(ea2, we0, add2(xA.x, xrA.x));
        l = fma2(f, C06, mul2(f & ABSM, C04));
        pacc = mul2(at0, l);
        f = fma2(ea2, we1, add2(xA.y, xrA.y));
        l = fma2(f, C06, mul2(f & ABSM, C04));
        pacc = fma2(at1, l, pacc);
        f = fma2(ea2, we2, add2(xB.x, xrB.x));
        l = fma2(f, C06, mul2(f & ABSM, C04));
        pacc = fma2(at2, l, pacc);
        f = fma2(ea2, we3, add2(xB.y, xrB.y));
        l = fma2(f, C06, mul2(f & ABSM, C04));
        pacc = fma2(at3, l, pacc);
        float plo, phi;
        upk2(pacc, plo, phi);
        float p = plo + phi;
        p += __shfl_xor_sync(0xffffffffu, p, 1);   // combine dim-halves

        if (act) {
            if (half == 0) {
                if (use_buf) psc[ii * 4 + h] = p;
                else         g_score[(long long)buf[0] * 0 + (long long)g_elist[start + ii] * 4 + h] = p;
            }
        } else {
            p = NEG_INF;
        }
        // batch max over the 4 edge slots
        float q = fmaxf(p, __shfl_xor_sync(0xffffffffu, p, 8));
        q = fmaxf(q, __shfl_xor_sync(0xffffffffu, q, 16));
        float mnew = fmaxf(m, q);
        float scale = __expf(m - mnew);             // first batch: exp(-inf)=0
        float ex = act ? __expf(p - mnew) : 0.f;
        den = den * scale + ex;
        u64 sc2 = pk2(scale, scale), ex2 = pk2(ex, ex);
        acc[0] = fma2(acc[0], sc2, mul2(xA.x, ex2));
        acc[1] = fma2(acc[1], sc2, mul2(xA.y, ex2));
        acc[2] = fma2(acc[2], sc2, mul2(xB.x, ex2));
        acc[3] = fma2(acc[3], sc2, mul2(xB.y, ex2));
        m = mnew;
    }

    // reduce across the 4 edge-slot lanes (fixed tree -> deterministic)
#pragma unroll
    for (int off = 8; off <= 16; off <<= 1) {
        den += __shfl_xor_sync(0xffffffffu, den, off);
#pragma unroll
        for (int j = 0; j < 4; j++) {
            u64 o = __shfl_xor_sync(0xffffffffu, acc[j], off);
            acc[j] = add2(acc[j], o);
        }
    }

    if (eslot == 0) {
        u64* sa = (u64*)&sacc[warp][dbase];
#pragma unroll
        for (int j = 0; j < 4; j++) sa[j] = acc[j];
    }
    __syncwarp();
    float2 av = *(const float2*)&sacc[warp][lane * 2];

    float deng = __shfl_sync(0xffffffffu, den, (lane >> 3) * 2);
    float dfin = deng + 1e-16f;
    float2 bo2 = *(const float2*)&bias_out[lane * 2];
    float ox = av.x / dfin + bo2.x;
    float oy = av.y / dfin + bo2.y;
    *(float2*)&out[n * 64 + lane * 2] = make_float2(ox, oy);   // pre-activation

    if (lane == 0) g_deg[n] = 0;   // reset for next call

    if (do_alpha) {
        float m0 = __shfl_sync(0xffffffffu, m, 0);
        float m1 = __shfl_sync(0xffffffffu, m, 2);
        float m2 = __shfl_sync(0xffffffffu, m, 4);
        float m3 = __shfl_sync(0xffffffffu, m, 6);
        float d0 = __shfl_sync(0xffffffffu, den, 0) + 1e-16f;
        float d1 = __shfl_sync(0xffffffffu, den, 2) + 1e-16f;
        float d2 = __shfl_sync(0xffffffffu, den, 4) + 1e-16f;
        float d3 = __shfl_sync(0xffffffffu, den, 6) + 1e-16f;
        for (int i = lane; i < deg; i += 32) {
            int e = use_buf ? buf[i] : g_elist[start + i];
            float4 s4 = use_buf ? *(const float4*)&psc[i * 4]
                                : *(const float4*)&g_score[(long long)e * 4];
            float4 a;
            a.x = __expf(s4.x - m0) / d0;
            a.y = __expf(s4.y - m1) / d1;
            a.z = __expf(s4.z - m2) / d2;
            a.w = __expf(s4.w - m3) / d3;
            *(float4*)&out[AL_OFF + (long long)e * 4] = a;
        }
    }
}

// ---------------- K4: residual + ELU epilogue ----------------
__global__ void k_post(float* __restrict__ out) {
    int i = blockIdx.x * blockDim.x + threadIdx.x;
    if (i < NN * HDIM / 4) {
        float4 o = *(const float4*)&out[i * 4];
        float4 r = *(const float4*)&g_res[i * 4];
        float vx = o.x + r.x, vy = o.y + r.y, vz = o.z + r.z, vw = o.w + r.w;
        vx = vx > 0.f ? vx : expm1f(vx);
        vy = vy > 0.f ? vy : expm1f(vy);
        vz = vz > 0.f ? vz : expm1f(vz);
        vw = vw > 0.f ? vw : expm1f(vw);
        *(float4*)&out[i * 4] = make_float4(vx, vy, vz, vw);
    }
}

// ---------------- launch ----------------
extern "C" void kernel_launch(void* const* d_in, const int* in_sizes, int n_in,
                              void* d_out, int out_size) {
    const float* x         = (const float*)d_in[0];
    const int*   ei        = (const int*)d_in[1];
    const float* edge_attr = (const float*)d_in[2];
    const float* Wl        = (const float*)d_in[3];
    const float* bl        = (const float*)d_in[4];
    const float* Wr        = (const float*)d_in[5];
    const float* br        = (const float*)d_in[6];
    const float* We        = (const float*)d_in[7];
    const float* att       = (const float*)d_in[8];
    const float* bias_out  = (const float*)d_in[9];
    const float* Wres      = (const float*)d_in[10];
    const float* bres      = (const float*)d_in[11];
    float* out = (float*)d_out;

    int write_ei = (out_size >= 4800000);
    int do_alpha = (out_size >= 8000000);

    static cudaStream_t s2 = 0, s3 = 0;
    static cudaEvent_t evA = 0, evB = 0, evC = 0;
    if (!s2) {
        cudaStreamCreateWithFlags(&s2, cudaStreamNonBlocking);
        cudaStreamCreateWithFlags(&s3, cudaStreamNonBlocking);
        cudaEventCreateWithFlags(&evA, cudaEventDisableTiming);
        cudaEventCreateWithFlags(&evB, cudaEventDisableTiming);
        cudaEventCreateWithFlags(&evC, cudaEventDisableTiming);
    }

    cudaEventRecord(evA, 0);
    cudaStreamWaitEvent(s2, evA, 0);
    cudaStreamWaitEvent(s3, evA, 0);

    // s2: xl/xr projections (gate for k_node); s3: residual projection (gate for k_post)
    k_proj2<<<(NN + 63) / 64, 256, 0, s2>>>(x, Wl, bl, Wr, br);
    cudaEventRecord(evB, s2);
    k_res<<<(NN + 31) / 32, 64, 0, s3>>>(x, Wres, bres);
    cudaEventRecord(evC, s3);

    // stream 0: convert -> CSR (+src/ea pre-gather)
    k_convert<<<(NE + 255) / 256, 256>>>(ei, out, write_ei);
    k_csr<<<NBLK, 256>>>(edge_attr);

    // node pass: needs CSR (stream order) + xl/xr
    cudaStreamWaitEvent(0, evB, 0);
    k_node<<<NN / 4, 128>>>(We, att, bias_out, out, do_alpha);

    // epilogue: needs node output + residual projection
    cudaStreamWaitEvent(0, evC, 0);
    k_post<<<(NN * HDIM / 4 + 255) / 256, 256>>>(out);
}